// round 12
// baseline (speedup 1.0000x reference)
#include <cuda_runtime.h>
#include <cuda_fp16.h>
#include <mma.h>
#include <cstdint>

using namespace nvcuda;

#define NE 8
#define NTOK 8192
#define DDIM 1024
#define HDIM 2048
#define ODIM 1024
#define OUTC (ODIM + NE)   // 1032

#define BM 128
#define BN 128
#define BK 64
#define NTHREADS 128       // 4 warps, 2x2 grid of 64x64 warp tiles
#define NSTAGE 3

// smem strides in HALF elements
#define A_STRIDE 72        // 64 + 8 pad -> 144B rows
#define B_STRIDE 136       // 128 + 8 pad -> 272B rows
#define C_STRIDE 136       // floats
#define A_STAGE_BYTES (BM * A_STRIDE * 2)   // 18432
#define B_STAGE_BYTES (BK * B_STRIDE * 2)   // 17408
#define SMEM_A_OFF 0
#define SMEM_B_OFF (NSTAGE * A_STAGE_BYTES)                   // 55296
#define SMEM_STAGE_END (SMEM_B_OFF + NSTAGE * B_STAGE_BYTES)  // 107520
#define SMEM_PERM_OFF SMEM_STAGE_END                          // 107520
#define SMEM_BYTES (SMEM_PERM_OFF + BM * 4)                   // 108032

#define PERM_CAP (NTOK + NE * BM)   // 9216
#define MAXTILES (PERM_CAP / BM)    // 72

// conversion chunk counts (8 floats per chunk)
#define N8_X  ((size_t)NTOK * DDIM / 8)
#define N8_W1 ((size_t)NE * DDIM * HDIM / 8)
#define N8_W2 ((size_t)NE * HDIM * ODIM / 8)
#define N8_XW1 (N8_X + N8_W1)
#define PRE_CVT_BLOCKS 768
#define CVT_ROWS 8          // gemm1: 8*16 = 128 first-wave cvt blocks

// ---- scratch (__device__ globals; no allocations allowed) ----
__device__ int    g_padoff[NE];
__device__ int    g_padcount[NE];
__device__ int    g_tile_e [MAXTILES];
__device__ int    g_tile_r0[MAXTILES];
__device__ int    g_ntiles;
__device__ int    g_perm[PERM_CAP];
__device__ __half g_xh [(size_t)NTOK * DDIM];
__device__ __half g_w1h[(size_t)NE * DDIM * HDIM];
__device__ __half g_w2h[(size_t)NE * HDIM * ODIM];
__device__ __half g_hh [(size_t)PERM_CAP * HDIM];

// ---- helpers ----
__device__ __forceinline__ uint32_t smem_u32(const void* p) {
    uint32_t a;
    asm("{ .reg .u64 t; cvta.to.shared.u64 t, %1; cvt.u32.u64 %0, t; }" : "=r"(a) : "l"(p));
    return a;
}
__device__ __forceinline__ void cp16(uint32_t dst, const void* src) {
    asm volatile("cp.async.cg.shared.global [%0], [%1], 16;\n" :: "r"(dst), "l"(src));
}
#define CP_COMMIT() asm volatile("cp.async.commit_group;\n" ::: "memory")
#define CP_WAIT1()  asm volatile("cp.async.wait_group 1;\n" ::: "memory")

__device__ __forceinline__ void cvt_chunk(const float* __restrict__ src,
                                          __half* __restrict__ dst, size_t j) {
    float4 v0 = reinterpret_cast<const float4*>(src)[2 * j];
    float4 v1 = reinterpret_cast<const float4*>(src)[2 * j + 1];
    __half2 h0 = __floats2half2_rn(v0.x, v0.y);
    __half2 h1 = __floats2half2_rn(v0.z, v0.w);
    __half2 h2 = __floats2half2_rn(v1.x, v1.y);
    __half2 h3 = __floats2half2_rn(v1.z, v1.w);
    uint4 pk;
    pk.x = *reinterpret_cast<uint32_t*>(&h0);
    pk.y = *reinterpret_cast<uint32_t*>(&h1);
    pk.z = *reinterpret_cast<uint32_t*>(&h2);
    pk.w = *reinterpret_cast<uint32_t*>(&h3);
    reinterpret_cast<uint4*>(dst)[j] = pk;
}

// ---------------- k_pre: block 0 = routing + tile table + onehot; blocks 1.. = cvt x & W1 ----------------
__global__ void __launch_bounds__(1024) k_pre(const int* __restrict__ eidx,
                                              const float* __restrict__ x,
                                              const float* __restrict__ W1,
                                              float* __restrict__ out) {
    int tid = threadIdx.x;
    if (blockIdx.x == 0) {
        __shared__ int scount[NE];
        __shared__ int soff[NE];
        __shared__ int scursor[NE];

        if (tid < NE) scount[tid] = 0;
        __syncthreads();

        for (int n = tid; n < NTOK; n += 1024) atomicAdd(&scount[eidx[n]], 1);
        __syncthreads();

        if (tid == 0) {
            int acc = 0, nt = 0;
            for (int e = 0; e < NE; e++) {
                int c = scount[e];
                int pc = ((c + BM - 1) / BM) * BM;
                soff[e] = acc; scursor[e] = acc;
                g_padoff[e] = acc; g_padcount[e] = pc;
                for (int r = 0; r < pc; r += BM) {
                    g_tile_e[nt] = e;
                    g_tile_r0[nt] = r;
                    nt++;
                }
                acc += pc;
            }
            g_ntiles = nt;
        }
        __syncthreads();

        {
            int e = tid >> 7;
            int l = tid & 127;
            int c  = scount[e];
            int pc = g_padcount[e];
            for (int i = c + l; i < pc; i += 128) g_perm[soff[e] + i] = -1;
        }

        for (int n = tid; n < NTOK; n += 1024) {
            int e = eidx[n];
            int p = atomicAdd(&scursor[e], 1);
            g_perm[p] = n;
            float4 lo = make_float4(e == 0 ? 1.f : 0.f, e == 1 ? 1.f : 0.f,
                                    e == 2 ? 1.f : 0.f, e == 3 ? 1.f : 0.f);
            float4 hi = make_float4(e == 4 ? 1.f : 0.f, e == 5 ? 1.f : 0.f,
                                    e == 6 ? 1.f : 0.f, e == 7 ? 1.f : 0.f);
            float* row = out + (size_t)n * OUTC + ODIM;
            *reinterpret_cast<float4*>(row)     = lo;
            *reinterpret_cast<float4*>(row + 4) = hi;
        }
    } else {
        size_t stride = (size_t)(gridDim.x - 1) * 1024;
        for (size_t i = (size_t)(blockIdx.x - 1) * 1024 + tid; i < N8_XW1; i += stride) {
            if (i < N8_X) cvt_chunk(x, g_xh, i);
            else          cvt_chunk(W1, g_w1h, i - N8_X);
        }
    }
}

// ---------------- fragments ----------------
using FragA = wmma::fragment<wmma::matrix_a, 16, 16, 16, __half, wmma::row_major>;
using FragB = wmma::fragment<wmma::matrix_b, 16, 16, 16, __half, wmma::row_major>;
using FragC = wmma::fragment<wmma::accumulator, 16, 16, 16, float>;

// ---------------- fp16 grouped GEMM: CTA 128x128x64, 4 warps of 64x64, 2 CTA/SM ----------------
template<int KDIM, int WLD, bool GATHER, bool SCATTER, bool CVTW2>
__global__ void __launch_bounds__(NTHREADS, 2) k_gemm(
    const float* __restrict__ bias, float* __restrict__ dst,
    const float* __restrict__ w2raw)
{
    int tid = threadIdx.x;

    if (CVTW2 && blockIdx.y < CVT_ROWS) {
        size_t nb  = (size_t)CVT_ROWS * gridDim.x;
        size_t bid = (size_t)blockIdx.y * gridDim.x + blockIdx.x;
        for (size_t j = bid * NTHREADS + tid; j < N8_W2; j += nb * NTHREADS)
            cvt_chunk(w2raw, g_w2h, j);
        return;
    }

    int ty = CVTW2 ? (int)blockIdx.y - CVT_ROWS : (int)blockIdx.y;
    if (ty >= g_ntiles) return;
    int e    = g_tile_e[ty];
    int row0 = g_tile_r0[ty];
    int base = g_padoff[e];
    int n0   = blockIdx.x * BN;

    const __half* __restrict__ Asrc = GATHER ? g_xh : g_hh;
    const __half* __restrict__ Wb   = (GATHER ? g_w1h : g_w2h) + (size_t)e * KDIM * WLD;
    const float*  __restrict__ be   = bias + (size_t)e * WLD;

    extern __shared__ char smem[];
    uint32_t smem_base = smem_u32(smem);
    int* sperm = (int*)(smem + SMEM_PERM_OFF);
    float* sC  = (float*)smem;

    int warp = tid >> 5;
    int wr   = warp >> 1;   // 0..1: 64-row band
    int wc   = warp & 1;    // 0..1: 64-col band

    if (tid < BM) sperm[tid] = g_perm[base + row0 + tid];
    __syncthreads();

    FragC acc[4][4];
    #pragma unroll
    for (int i = 0; i < 4; i++)
        #pragma unroll
        for (int j = 0; j < 4; j++)
            wmma::fill_fragment(acc[i][j], 0.0f);

    const int KT = KDIM / BK;   // gemm1: 16, gemm2: 32

    auto load_stage = [&](int st) {
        if (st < KT) {
            int k0  = st * BK;
            int buf = st % NSTAGE;
            uint32_t aB = smem_base + SMEM_A_OFF + buf * A_STAGE_BYTES;
            uint32_t bB = smem_base + SMEM_B_OFF + buf * B_STAGE_BYTES;
            #pragma unroll
            for (int i = 0; i < 8; i++) {          // A: 128 rows x 64 halves = 1024 x 16B
                int lin = i * NTHREADS + tid;
                int r = lin >> 3, c8 = lin & 7;
                const __half* src;
                if (GATHER) {
                    int t = sperm[r]; if (t < 0) t = 0;
                    src = Asrc + (size_t)t * KDIM + k0 + c8 * 8;
                } else {
                    src = Asrc + (size_t)(base + row0 + r) * KDIM + k0 + c8 * 8;
                }
                cp16(aB + r * (A_STRIDE * 2) + c8 * 16, src);
            }
            #pragma unroll
            for (int i = 0; i < 8; i++) {          // B: 64 rows x 128 halves = 1024 x 16B
                int lin = i * NTHREADS + tid;
                int r = lin >> 4, c8 = lin & 15;
                cp16(bB + r * (B_STRIDE * 2) + c8 * 16,
                     Wb + (size_t)(k0 + r) * WLD + n0 + c8 * 8);
            }
        }
        CP_COMMIT();
    };

    // preload 2 stages (3rd buffer free)
    load_stage(0); load_stage(1);

    for (int s = 0; s < KT; s++) {
        CP_WAIT1();                  // <=1 newer group pending -> stage s resident
        __syncthreads();             // stage-s copies visible; compute(s-1) done
        load_stage(s + 2);           // buf (s+2)%3 == (s-1)%3 — proven drained
        int buf = s % NSTAGE;
        const __half* A0 = (const __half*)(smem + SMEM_A_OFF + buf * A_STAGE_BYTES);
        const __half* B0 = (const __half*)(smem + SMEM_B_OFF + buf * B_STAGE_BYTES);
        #pragma unroll
        for (int kk = 0; kk < BK; kk += 16) {
            FragA a[4];
            FragB b[4];
            #pragma unroll
            for (int i = 0; i < 4; i++)
                wmma::load_matrix_sync(a[i], A0 + (wr * 64 + i * 16) * A_STRIDE + kk, A_STRIDE);
            #pragma unroll
            for (int j = 0; j < 4; j++)
                wmma::load_matrix_sync(b[j], B0 + kk * B_STRIDE + wc * 64 + j * 16, B_STRIDE);
            #pragma unroll
            for (int i = 0; i < 4; i++)
                #pragma unroll
                for (int j = 0; j < 4; j++)
                    wmma::mma_sync(acc[i][j], a[i], b[j], acc[i][j]);
        }
    }

    // ---- epilogue: stage full 128x128 C in smem (union over stage buffers) ----
    __syncthreads();
    #pragma unroll
    for (int i = 0; i < 4; i++)
        #pragma unroll
        for (int j = 0; j < 4; j++)
            wmma::store_matrix_sync(sC + (wr * 64 + i * 16) * C_STRIDE + wc * 64 + j * 16,
                                    acc[i][j], C_STRIDE, wmma::mem_row_major);
    __syncthreads();

    #pragma unroll
    for (int i = 0; i < 32; i++) {              // 128x128 = 4096 float4 chunks / 128 thr
        int lin = i * NTHREADS + tid;
        int r   = lin >> 5;
        int c4  = lin & 31;
        int t   = sperm[r];
        float4 v = *reinterpret_cast<const float4*>(sC + r * C_STRIDE + c4 * 4);
        const float4 bb = *reinterpret_cast<const float4*>(&be[n0 + c4 * 4]);
        v.x += bb.x; v.y += bb.y; v.z += bb.z; v.w += bb.w;
        if (SCATTER) {
            if (t >= 0) {
                *reinterpret_cast<float4*>(&dst[(size_t)t * OUTC + n0 + c4 * 4]) = v;
            }
        } else {
            __half2 lo = __floats2half2_rn(v.x, v.y);
            __half2 hi = __floats2half2_rn(v.z, v.w);
            uint2 pk;
            pk.x = *reinterpret_cast<uint32_t*>(&lo);
            pk.y = *reinterpret_cast<uint32_t*>(&hi);
            *reinterpret_cast<uint2*>(
                g_hh + (size_t)(base + row0 + r) * WLD + n0 + c4 * 4) = pk;
        }
    }
}

// ---------------- launch ----------------
extern "C" void kernel_launch(void* const* d_in, const int* in_sizes, int n_in,
                              void* d_out, int out_size) {
    const float* x    = (const float*)d_in[0];
    const float* W1   = (const float*)d_in[1];
    const float* b1   = (const float*)d_in[2];
    const float* W2   = (const float*)d_in[3];
    const float* b2   = (const float*)d_in[4];
    const int*   eidx = (const int*)  d_in[5];
    float* out = (float*)d_out;

    cudaFuncSetAttribute((const void*)k_gemm<DDIM, HDIM, true, false, true>,
                         cudaFuncAttributeMaxDynamicSharedMemorySize, SMEM_BYTES);
    cudaFuncSetAttribute((const void*)k_gemm<HDIM, ODIM, false, true, false>,
                         cudaFuncAttributeMaxDynamicSharedMemorySize, SMEM_BYTES);

    k_pre<<<1 + PRE_CVT_BLOCKS, 1024>>>(eidx, x, W1, out);

    dim3 g1(HDIM / BN, CVT_ROWS + MAXTILES, 1);   // (16, 80)
    k_gemm<DDIM, HDIM, true, false, true><<<g1, NTHREADS, SMEM_BYTES>>>(b1, nullptr, W2);

    dim3 g2(ODIM / BN, MAXTILES, 1);              // (8, 72)
    k_gemm<HDIM, ODIM, false, true, false><<<g2, NTHREADS, SMEM_BYTES>>>(b2, out, nullptr);
}

// round 13
// speedup vs baseline: 1.0300x; 1.0300x over previous
#include <cuda_runtime.h>
#include <cuda_fp16.h>
#include <mma.h>
#include <cstdint>

using namespace nvcuda;

#define NE 8
#define NTOK 8192
#define DDIM 1024
#define HDIM 2048
#define ODIM 1024
#define OUTC (ODIM + NE)   // 1032

#define BM 128
#define BN 128
#define BK 32
#define NTHREADS 128       // 4 warps, 2x2 grid of 64x64 warp tiles
#define NSTAGE 5

// smem strides in HALF elements (frozen champion config + 1 extra stage)
#define A_STRIDE 40        // 32 + 8 pad -> 80B rows
#define B_STRIDE 136       // 128 + 8 pad -> 272B rows
#define C_STRIDE 136       // floats
#define A_STAGE_BYTES (BM * A_STRIDE * 2)   // 10240
#define B_STAGE_BYTES (BK * B_STRIDE * 2)   // 8704
#define SMEM_A_OFF 0
#define SMEM_B_OFF (NSTAGE * A_STAGE_BYTES)                   // 51200
#define SMEM_STAGE_END (SMEM_B_OFF + NSTAGE * B_STAGE_BYTES)  // 94720
#define SMEM_PERM_OFF SMEM_STAGE_END                          // 94720
#define SMEM_BYTES (SMEM_PERM_OFF + BM * 4)                   // 95232

#define PERM_CAP (NTOK + NE * BM)   // 9216
#define MAXTILES (PERM_CAP / BM)    // 72

// conversion chunk counts (8 floats per chunk)
#define N8_X  ((size_t)NTOK * DDIM / 8)
#define N8_W1 ((size_t)NE * DDIM * HDIM / 8)
#define N8_W2 ((size_t)NE * HDIM * ODIM / 8)
#define N8_XW1 (N8_X + N8_W1)
#define N8_XW1_HALF (N8_XW1 / 2)
#define PRE_CVT_BLOCKS 768
#define CVT_ROWS 8          // gemm1: 8*16 = 128 first-wave cvt blocks

// ---- scratch (__device__ globals; no allocations allowed) ----
__device__ int    g_padoff[NE];
__device__ int    g_padcount[NE];
__device__ int    g_tile_e [MAXTILES];
__device__ int    g_tile_r0[MAXTILES];
__device__ int    g_ntiles;
__device__ int    g_perm[PERM_CAP];
__device__ __half g_xh [(size_t)NTOK * DDIM];
__device__ __half g_w1h[(size_t)NE * DDIM * HDIM];
__device__ __half g_w2h[(size_t)NE * HDIM * ODIM];
__device__ __half g_hh [(size_t)PERM_CAP * HDIM];

// ---- helpers ----
__device__ __forceinline__ uint32_t smem_u32(const void* p) {
    uint32_t a;
    asm("{ .reg .u64 t; cvta.to.shared.u64 t, %1; cvt.u32.u64 %0, t; }" : "=r"(a) : "l"(p));
    return a;
}
__device__ __forceinline__ void cp16(uint32_t dst, const void* src) {
    asm volatile("cp.async.cg.shared.global [%0], [%1], 16;\n" :: "r"(dst), "l"(src));
}
#define CP_COMMIT() asm volatile("cp.async.commit_group;\n" ::: "memory")
#define CP_WAIT3()  asm volatile("cp.async.wait_group 3;\n" ::: "memory")

__device__ __forceinline__ void cvt_chunk(const float* __restrict__ src,
                                          __half* __restrict__ dst, size_t j) {
    float4 v0 = reinterpret_cast<const float4*>(src)[2 * j];
    float4 v1 = reinterpret_cast<const float4*>(src)[2 * j + 1];
    __half2 h0 = __floats2half2_rn(v0.x, v0.y);
    __half2 h1 = __floats2half2_rn(v0.z, v0.w);
    __half2 h2 = __floats2half2_rn(v1.x, v1.y);
    __half2 h3 = __floats2half2_rn(v1.z, v1.w);
    uint4 pk;
    pk.x = *reinterpret_cast<uint32_t*>(&h0);
    pk.y = *reinterpret_cast<uint32_t*>(&h1);
    pk.z = *reinterpret_cast<uint32_t*>(&h2);
    pk.w = *reinterpret_cast<uint32_t*>(&h3);
    reinterpret_cast<uint4*>(dst)[j] = pk;
}

// chunk index -> (src,dst,local j) over the concatenated x|W1 space
__device__ __forceinline__ void cvt_xw1(const float* __restrict__ x,
                                        const float* __restrict__ W1, size_t i) {
    if (i < N8_X) cvt_chunk(x, g_xh, i);
    else          cvt_chunk(W1, g_w1h, i - N8_X);
}

// ---------------- k_pre: block 0 = routing + tile table + onehot; blocks 1.. = cvt x & W1 ----------------
__global__ void __launch_bounds__(1024) k_pre(const int* __restrict__ eidx,
                                              const float* __restrict__ x,
                                              const float* __restrict__ W1,
                                              float* __restrict__ out) {
    int tid = threadIdx.x;
    if (blockIdx.x == 0) {
        __shared__ int scount[NE];
        __shared__ int soff[NE];
        __shared__ int scursor[NE];

        if (tid < NE) scount[tid] = 0;
        __syncthreads();

        for (int n = tid; n < NTOK; n += 1024) atomicAdd(&scount[eidx[n]], 1);
        __syncthreads();

        if (tid == 0) {
            int acc = 0, nt = 0;
            for (int e = 0; e < NE; e++) {
                int c = scount[e];
                int pc = ((c + BM - 1) / BM) * BM;
                soff[e] = acc; scursor[e] = acc;
                g_padoff[e] = acc; g_padcount[e] = pc;
                for (int r = 0; r < pc; r += BM) {
                    g_tile_e[nt] = e;
                    g_tile_r0[nt] = r;
                    nt++;
                }
                acc += pc;
            }
            g_ntiles = nt;
        }
        __syncthreads();

        {
            int e = tid >> 7;
            int l = tid & 127;
            int c  = scount[e];
            int pc = g_padcount[e];
            for (int i = c + l; i < pc; i += 128) g_perm[soff[e] + i] = -1;
        }

        for (int n = tid; n < NTOK; n += 1024) {
            int e = eidx[n];
            int p = atomicAdd(&scursor[e], 1);
            g_perm[p] = n;
            float4 lo = make_float4(e == 0 ? 1.f : 0.f, e == 1 ? 1.f : 0.f,
                                    e == 2 ? 1.f : 0.f, e == 3 ? 1.f : 0.f);
            float4 hi = make_float4(e == 4 ? 1.f : 0.f, e == 5 ? 1.f : 0.f,
                                    e == 6 ? 1.f : 0.f, e == 7 ? 1.f : 0.f);
            float* row = out + (size_t)n * OUTC + ODIM;
            *reinterpret_cast<float4*>(row)     = lo;
            *reinterpret_cast<float4*>(row + 4) = hi;
        }
    } else {
        // MLP-4 conversion: two chunks (half the space apart) per iteration
        size_t stride = (size_t)(gridDim.x - 1) * 1024;
        for (size_t i = (size_t)(blockIdx.x - 1) * 1024 + tid; i < N8_XW1_HALF; i += stride) {
            cvt_xw1(x, W1, i);
            cvt_xw1(x, W1, i + N8_XW1_HALF);
        }
    }
}

// ---------------- fragments ----------------
using FragA = wmma::fragment<wmma::matrix_a, 16, 16, 16, __half, wmma::row_major>;
using FragB = wmma::fragment<wmma::matrix_b, 16, 16, 16, __half, wmma::row_major>;
using FragC = wmma::fragment<wmma::accumulator, 16, 16, 16, float>;

// ---------------- fp16 grouped GEMM: CTA 128x128x32, 4 warps of 64x64, 2 CTA/SM (FROZEN CORE) ----------------
template<int KDIM, int WLD, bool GATHER, bool SCATTER, bool CVTW2>
__global__ void __launch_bounds__(NTHREADS, 2) k_gemm(
    const float* __restrict__ bias, float* __restrict__ dst,
    const float* __restrict__ w2raw)
{
    int tid = threadIdx.x;

    if (CVTW2 && blockIdx.y < CVT_ROWS) {
        size_t nb  = (size_t)CVT_ROWS * gridDim.x;
        size_t bid = (size_t)blockIdx.y * gridDim.x + blockIdx.x;
        size_t step = nb * NTHREADS;
        size_t half = N8_W2 / 2;
        for (size_t j = bid * NTHREADS + tid; j < half; j += step) {
            cvt_chunk(w2raw, g_w2h, j);
            cvt_chunk(w2raw, g_w2h, j + half);
        }
        return;
    }

    int ty = CVTW2 ? (int)blockIdx.y - CVT_ROWS : (int)blockIdx.y;
    if (ty >= g_ntiles) return;
    int e    = g_tile_e[ty];
    int row0 = g_tile_r0[ty];
    int base = g_padoff[e];
    int n0   = blockIdx.x * BN;

    const __half* __restrict__ Asrc = GATHER ? g_xh : g_hh;
    const __half* __restrict__ Wb   = (GATHER ? g_w1h : g_w2h) + (size_t)e * KDIM * WLD;
    const float*  __restrict__ be   = bias + (size_t)e * WLD;

    extern __shared__ char smem[];
    uint32_t smem_base = smem_u32(smem);
    int* sperm = (int*)(smem + SMEM_PERM_OFF);
    float* sC  = (float*)smem;

    int warp = tid >> 5;
    int wr   = warp >> 1;   // 0..1: 64-row band
    int wc   = warp & 1;    // 0..1: 64-col band

    if (tid < BM) sperm[tid] = g_perm[base + row0 + tid];
    __syncthreads();

    FragC acc[4][4];
    #pragma unroll
    for (int i = 0; i < 4; i++)
        #pragma unroll
        for (int j = 0; j < 4; j++)
            wmma::fill_fragment(acc[i][j], 0.0f);

    const int KT = KDIM / BK;

    auto load_stage = [&](int st) {
        if (st < KT) {
            int k0  = st * BK;
            int buf = st % NSTAGE;
            uint32_t aB = smem_base + SMEM_A_OFF + buf * A_STAGE_BYTES;
            uint32_t bB = smem_base + SMEM_B_OFF + buf * B_STAGE_BYTES;
            #pragma unroll
            for (int i = 0; i < 4; i++) {          // A: 128 rows x 32 halves = 512 x 16B
                int lin = i * NTHREADS + tid;
                int r = lin >> 2, c8 = lin & 3;
                const __half* src;
                if (GATHER) {
                    int t = sperm[r]; if (t < 0) t = 0;
                    src = Asrc + (size_t)t * KDIM + k0 + c8 * 8;
                } else {
                    src = Asrc + (size_t)(base + row0 + r) * KDIM + k0 + c8 * 8;
                }
                cp16(aB + r * (A_STRIDE * 2) + c8 * 16, src);
            }
            #pragma unroll
            for (int i = 0; i < 4; i++) {          // B: 32 rows x 128 halves = 512 x 16B
                int lin = i * NTHREADS + tid;
                int r = lin >> 4, c8 = lin & 15;
                cp16(bB + r * (B_STRIDE * 2) + c8 * 16,
                     Wb + (size_t)(k0 + r) * WLD + n0 + c8 * 8);
            }
        }
        CP_COMMIT();
    };

    // preload 4 stages (5th buffer free)
    load_stage(0); load_stage(1); load_stage(2); load_stage(3);

    for (int s = 0; s < KT; s++) {
        CP_WAIT3();                  // <=3 newer groups pending -> stage s resident
        __syncthreads();             // stage-s copies visible; compute(s-1) done
        load_stage(s + 4);           // buf (s+4)%5 == (s-1)%5 — proven drained
        int buf = s % NSTAGE;
        const __half* A0 = (const __half*)(smem + SMEM_A_OFF + buf * A_STAGE_BYTES);
        const __half* B0 = (const __half*)(smem + SMEM_B_OFF + buf * B_STAGE_BYTES);
        #pragma unroll
        for (int kk = 0; kk < BK; kk += 16) {
            FragA a[4];
            FragB b[4];
            #pragma unroll
            for (int i = 0; i < 4; i++)
                wmma::load_matrix_sync(a[i], A0 + (wr * 64 + i * 16) * A_STRIDE + kk, A_STRIDE);
            #pragma unroll
            for (int j = 0; j < 4; j++)
                wmma::load_matrix_sync(b[j], B0 + kk * B_STRIDE + wc * 64 + j * 16, B_STRIDE);
            #pragma unroll
            for (int i = 0; i < 4; i++)
                #pragma unroll
                for (int j = 0; j < 4; j++)
                    wmma::mma_sync(acc[i][j], a[i], b[j], acc[i][j]);
        }
    }

    // ---- epilogue: stage full 128x128 C in smem (union over stage buffers) ----
    __syncthreads();
    #pragma unroll
    for (int i = 0; i < 4; i++)
        #pragma unroll
        for (int j = 0; j < 4; j++)
            wmma::store_matrix_sync(sC + (wr * 64 + i * 16) * C_STRIDE + wc * 64 + j * 16,
                                    acc[i][j], C_STRIDE, wmma::mem_row_major);
    __syncthreads();

    #pragma unroll
    for (int i = 0; i < 32; i++) {              // 128x128 = 4096 float4 chunks / 128 thr
        int lin = i * NTHREADS + tid;
        int r   = lin >> 5;
        int c4  = lin & 31;
        int t   = sperm[r];
        float4 v = *reinterpret_cast<const float4*>(sC + r * C_STRIDE + c4 * 4);
        const float4 bb = *reinterpret_cast<const float4*>(&be[n0 + c4 * 4]);
        v.x += bb.x; v.y += bb.y; v.z += bb.z; v.w += bb.w;
        if (SCATTER) {
            if (t >= 0) {
                *reinterpret_cast<float4*>(&dst[(size_t)t * OUTC + n0 + c4 * 4]) = v;
            }
        } else {
            __half2 lo = __floats2half2_rn(v.x, v.y);
            __half2 hi = __floats2half2_rn(v.z, v.w);
            uint2 pk;
            pk.x = *reinterpret_cast<uint32_t*>(&lo);
            pk.y = *reinterpret_cast<uint32_t*>(&hi);
            *reinterpret_cast<uint2*>(
                g_hh + (size_t)(base + row0 + r) * WLD + n0 + c4 * 4) = pk;
        }
    }
}

// ---------------- launch ----------------
extern "C" void kernel_launch(void* const* d_in, const int* in_sizes, int n_in,
                              void* d_out, int out_size) {
    const float* x    = (const float*)d_in[0];
    const float* W1   = (const float*)d_in[1];
    const float* b1   = (const float*)d_in[2];
    const float* W2   = (const float*)d_in[3];
    const float* b2   = (const float*)d_in[4];
    const int*   eidx = (const int*)  d_in[5];
    float* out = (float*)d_out;

    cudaFuncSetAttribute((const void*)k_gemm<DDIM, HDIM, true, false, true>,
                         cudaFuncAttributeMaxDynamicSharedMemorySize, SMEM_BYTES);
    cudaFuncSetAttribute((const void*)k_gemm<HDIM, ODIM, false, true, false>,
                         cudaFuncAttributeMaxDynamicSharedMemorySize, SMEM_BYTES);

    k_pre<<<1 + PRE_CVT_BLOCKS, 1024>>>(eidx, x, W1, out);

    dim3 g1(HDIM / BN, CVT_ROWS + MAXTILES, 1);   // (16, 80)
    k_gemm<DDIM, HDIM, true, false, true><<<g1, NTHREADS, SMEM_BYTES>>>(b1, nullptr, W2);

    dim3 g2(ODIM / BN, MAXTILES, 1);              // (8, 72)
    k_gemm<HDIM, ODIM, false, true, false><<<g2, NTHREADS, SMEM_BYTES>>>(b2, out, nullptr);
}

// round 14
// speedup vs baseline: 1.0332x; 1.0031x over previous
#include <cuda_runtime.h>
#include <cuda_fp16.h>
#include <mma.h>
#include <cstdint>

using namespace nvcuda;

#define NE 8
#define NTOK 8192
#define DDIM 1024
#define HDIM 2048
#define ODIM 1024
#define OUTC (ODIM + NE)   // 1032

#define BM 128
#define BN 128
#define BK 32
#define NTHREADS 128       // 4 warps, 2x2 grid of 64x64 warp tiles
#define NSTAGE 4

// smem strides in HALF elements (frozen R11 champion config)
#define A_STRIDE 40        // 32 + 8 pad -> 80B rows
#define B_STRIDE 136       // 128 + 8 pad -> 272B rows
#define C_STRIDE 136       // floats
#define A_STAGE_BYTES (BM * A_STRIDE * 2)   // 10240
#define B_STAGE_BYTES (BK * B_STRIDE * 2)   // 8704
#define SMEM_A_OFF 0
#define SMEM_B_OFF (NSTAGE * A_STAGE_BYTES)                   // 40960
#define SMEM_STAGE_END (SMEM_B_OFF + NSTAGE * B_STAGE_BYTES)  // 75776
#define SMEM_PERM_OFF SMEM_STAGE_END                          // 75776
#define SMEM_BYTES (SMEM_PERM_OFF + BM * 4)                   // 76288

#define PERM_CAP (NTOK + NE * BM)   // 9216
#define MAXTILES (PERM_CAP / BM)    // 72

// conversion chunk counts (8 floats per chunk)
#define N8_X  ((size_t)NTOK * DDIM / 8)
#define N8_W1 ((size_t)NE * DDIM * HDIM / 8)
#define N8_W2 ((size_t)NE * HDIM * ODIM / 8)
#define N8_XW1 (N8_X + N8_W1)
#define PRE_CVT_BLOCKS 768

// fused kernel grid regions (y axis)
#define CVT_ROWS 8                          // y in [0,8): 128 W2-cvt blocks
#define G1_Y0 CVT_ROWS                      // y in [8,80): gemm1 tiles
#define G2_Y0 (CVT_ROWS + MAXTILES)         // y in [80,116): gemm2, 16 blocks/row
#define G2_ROWS ((MAXTILES * 8 + 15) / 16)  // 36
#define CVT_BLOCKS (CVT_ROWS * 16)          // 128

// ---- scratch (__device__ globals; no allocations allowed) ----
__device__ int    g_padoff[NE];
__device__ int    g_padcount[NE];
__device__ int    g_tile_e [MAXTILES];
__device__ int    g_tile_r0[MAXTILES];
__device__ int    g_ntiles;
__device__ int    g_perm[PERM_CAP];
__device__ int    g_done1[MAXTILES];   // gemm1 column-tiles completed per row tile
__device__ int    g_w2done;            // W2 cvt blocks completed
__device__ __half g_xh [(size_t)NTOK * DDIM];
__device__ __half g_w1h[(size_t)NE * DDIM * HDIM];
__device__ __half g_w2h[(size_t)NE * HDIM * ODIM];
__device__ __half g_hh [(size_t)PERM_CAP * HDIM];

// ---- helpers ----
__device__ __forceinline__ uint32_t smem_u32(const void* p) {
    uint32_t a;
    asm("{ .reg .u64 t; cvta.to.shared.u64 t, %1; cvt.u32.u64 %0, t; }" : "=r"(a) : "l"(p));
    return a;
}
__device__ __forceinline__ void cp16(uint32_t dst, const void* src) {
    asm volatile("cp.async.cg.shared.global [%0], [%1], 16;\n" :: "r"(dst), "l"(src));
}
#define CP_COMMIT() asm volatile("cp.async.commit_group;\n" ::: "memory")
#define CP_WAIT2()  asm volatile("cp.async.wait_group 2;\n" ::: "memory")

__device__ __forceinline__ void cvt_chunk(const float* __restrict__ src,
                                          __half* __restrict__ dst, size_t j) {
    float4 v0 = reinterpret_cast<const float4*>(src)[2 * j];
    float4 v1 = reinterpret_cast<const float4*>(src)[2 * j + 1];
    __half2 h0 = __floats2half2_rn(v0.x, v0.y);
    __half2 h1 = __floats2half2_rn(v0.z, v0.w);
    __half2 h2 = __floats2half2_rn(v1.x, v1.y);
    __half2 h3 = __floats2half2_rn(v1.z, v1.w);
    uint4 pk;
    pk.x = *reinterpret_cast<uint32_t*>(&h0);
    pk.y = *reinterpret_cast<uint32_t*>(&h1);
    pk.z = *reinterpret_cast<uint32_t*>(&h2);
    pk.w = *reinterpret_cast<uint32_t*>(&h3);
    reinterpret_cast<uint4*>(dst)[j] = pk;
}

// ---------------- k_pre: block 0 = routing + tile table + flags + onehot; blocks 1.. = cvt x & W1 ----------------
__global__ void __launch_bounds__(1024) k_pre(const int* __restrict__ eidx,
                                              const float* __restrict__ x,
                                              const float* __restrict__ W1,
                                              float* __restrict__ out) {
    int tid = threadIdx.x;
    if (blockIdx.x == 0) {
        __shared__ int scount[NE];
        __shared__ int soff[NE];
        __shared__ int scursor[NE];

        if (tid < NE) scount[tid] = 0;
        if (tid < MAXTILES) g_done1[tid] = 0;
        if (tid == 0) g_w2done = 0;
        __syncthreads();

        for (int n = tid; n < NTOK; n += 1024) atomicAdd(&scount[eidx[n]], 1);
        __syncthreads();

        if (tid == 0) {
            int acc = 0, nt = 0;
            for (int e = 0; e < NE; e++) {
                int c = scount[e];
                int pc = ((c + BM - 1) / BM) * BM;
                soff[e] = acc; scursor[e] = acc;
                g_padoff[e] = acc; g_padcount[e] = pc;
                for (int r = 0; r < pc; r += BM) {
                    g_tile_e[nt] = e;
                    g_tile_r0[nt] = r;
                    nt++;
                }
                acc += pc;
            }
            g_ntiles = nt;
        }
        __syncthreads();

        {
            int e = tid >> 7;
            int l = tid & 127;
            int c  = scount[e];
            int pc = g_padcount[e];
            for (int i = c + l; i < pc; i += 128) g_perm[soff[e] + i] = -1;
        }

        for (int n = tid; n < NTOK; n += 1024) {
            int e = eidx[n];
            int p = atomicAdd(&scursor[e], 1);
            g_perm[p] = n;
            float4 lo = make_float4(e == 0 ? 1.f : 0.f, e == 1 ? 1.f : 0.f,
                                    e == 2 ? 1.f : 0.f, e == 3 ? 1.f : 0.f);
            float4 hi = make_float4(e == 4 ? 1.f : 0.f, e == 5 ? 1.f : 0.f,
                                    e == 6 ? 1.f : 0.f, e == 7 ? 1.f : 0.f);
            float* row = out + (size_t)n * OUTC + ODIM;
            *reinterpret_cast<float4*>(row)     = lo;
            *reinterpret_cast<float4*>(row + 4) = hi;
        }
    } else {
        size_t stride = (size_t)(gridDim.x - 1) * 1024;
        for (size_t i = (size_t)(blockIdx.x - 1) * 1024 + tid; i < N8_XW1; i += stride) {
            if (i < N8_X) cvt_chunk(x, g_xh, i);
            else          cvt_chunk(W1, g_w1h, i - N8_X);
        }
    }
}

// ---------------- fragments ----------------
using FragA = wmma::fragment<wmma::matrix_a, 16, 16, 16, __half, wmma::row_major>;
using FragB = wmma::fragment<wmma::matrix_b, 16, 16, 16, __half, wmma::row_major>;
using FragC = wmma::fragment<wmma::accumulator, 16, 16, 16, float>;

// ---------------- frozen R11 GEMM tile body (runtime K / ld) ----------------
// GATHER=1: A rows gathered via perm from g_xh; output -> g_hh fp16 (+bias)
// GATHER=0: A contiguous from g_hh; output -> dst fp32 (+bias) scattered via perm
template<bool GATHER, bool SCATTER>
__device__ __forceinline__ void gemm_tile(
    int KDIM, int WLD, int e, int row0, int base, int n0,
    const __half* __restrict__ Asrc, const __half* __restrict__ Wbase,
    const float* __restrict__ bias, float* __restrict__ dst, char* smem)
{
    const __half* __restrict__ Wb = Wbase + (size_t)e * KDIM * WLD;
    const float*  __restrict__ be = bias + (size_t)e * WLD;

    uint32_t smem_base = smem_u32(smem);
    int* sperm = (int*)(smem + SMEM_PERM_OFF);
    float* sC  = (float*)smem;

    int tid  = threadIdx.x;
    int warp = tid >> 5;
    int wr   = warp >> 1;   // 0..1: 64-row band
    int wc   = warp & 1;    // 0..1: 64-col band

    if (tid < BM) sperm[tid] = g_perm[base + row0 + tid];
    __syncthreads();

    FragC acc[4][4];
    #pragma unroll
    for (int i = 0; i < 4; i++)
        #pragma unroll
        for (int j = 0; j < 4; j++)
            wmma::fill_fragment(acc[i][j], 0.0f);

    const int KT = KDIM / BK;

    auto load_stage = [&](int st) {
        if (st < KT) {
            int k0  = st * BK;
            int buf = st % NSTAGE;
            uint32_t aB = smem_base + SMEM_A_OFF + buf * A_STAGE_BYTES;
            uint32_t bB = smem_base + SMEM_B_OFF + buf * B_STAGE_BYTES;
            #pragma unroll
            for (int i = 0; i < 4; i++) {          // A: 128 rows x 32 halves = 512 x 16B
                int lin = i * NTHREADS + tid;
                int r = lin >> 2, c8 = lin & 3;
                const __half* src;
                if (GATHER) {
                    int t = sperm[r]; if (t < 0) t = 0;
                    src = Asrc + (size_t)t * KDIM + k0 + c8 * 8;
                } else {
                    src = Asrc + (size_t)(base + row0 + r) * KDIM + k0 + c8 * 8;
                }
                cp16(aB + r * (A_STRIDE * 2) + c8 * 16, src);
            }
            #pragma unroll
            for (int i = 0; i < 4; i++) {          // B: 32 rows x 128 halves = 512 x 16B
                int lin = i * NTHREADS + tid;
                int r = lin >> 4, c8 = lin & 15;
                cp16(bB + r * (B_STRIDE * 2) + c8 * 16,
                     Wb + (size_t)(k0 + r) * WLD + n0 + c8 * 8);
            }
        }
        CP_COMMIT();
    };

    load_stage(0); load_stage(1); load_stage(2);

    for (int s = 0; s < KT; s++) {
        CP_WAIT2();                  // stage s resident (this thread)
        __syncthreads();             // stage-s copies visible; compute(s-1) done
        load_stage(s + 3);           // refills buf (s-1)%4 — proven drained
        int buf = s % NSTAGE;
        const __half* A0 = (const __half*)(smem + SMEM_A_OFF + buf * A_STAGE_BYTES);
        const __half* B0 = (const __half*)(smem + SMEM_B_OFF + buf * B_STAGE_BYTES);
        #pragma unroll
        for (int kk = 0; kk < BK; kk += 16) {
            FragA a[4];
            FragB b[4];
            #pragma unroll
            for (int i = 0; i < 4; i++)
                wmma::load_matrix_sync(a[i], A0 + (wr * 64 + i * 16) * A_STRIDE + kk, A_STRIDE);
            #pragma unroll
            for (int j = 0; j < 4; j++)
                wmma::load_matrix_sync(b[j], B0 + kk * B_STRIDE + wc * 64 + j * 16, B_STRIDE);
            #pragma unroll
            for (int i = 0; i < 4; i++)
                #pragma unroll
                for (int j = 0; j < 4; j++)
                    wmma::mma_sync(acc[i][j], a[i], b[j], acc[i][j]);
        }
    }

    // ---- epilogue: stage full 128x128 C in smem (union over stage buffers) ----
    __syncthreads();
    #pragma unroll
    for (int i = 0; i < 4; i++)
        #pragma unroll
        for (int j = 0; j < 4; j++)
            wmma::store_matrix_sync(sC + (wr * 64 + i * 16) * C_STRIDE + wc * 64 + j * 16,
                                    acc[i][j], C_STRIDE, wmma::mem_row_major);
    __syncthreads();

    #pragma unroll
    for (int i = 0; i < 32; i++) {              // 128x128 = 4096 float4 chunks / 128 thr
        int lin = i * NTHREADS + tid;
        int r   = lin >> 5;
        int c4  = lin & 31;
        int t   = sperm[r];
        float4 v = *reinterpret_cast<const float4*>(sC + r * C_STRIDE + c4 * 4);
        const float4 bb = *reinterpret_cast<const float4*>(&be[n0 + c4 * 4]);
        v.x += bb.x; v.y += bb.y; v.z += bb.z; v.w += bb.w;
        if (SCATTER) {
            if (t >= 0) {
                *reinterpret_cast<float4*>(&dst[(size_t)t * OUTC + n0 + c4 * 4]) = v;
            }
        } else {
            __half2 lo = __floats2half2_rn(v.x, v.y);
            __half2 hi = __floats2half2_rn(v.z, v.w);
            uint2 pk;
            pk.x = *reinterpret_cast<uint32_t*>(&lo);
            pk.y = *reinterpret_cast<uint32_t*>(&hi);
            *reinterpret_cast<uint2*>(
                g_hh + (size_t)(base + row0 + r) * WLD + n0 + c4 * 4) = pk;
        }
    }
}

// ---------------- fused kernel: W2-cvt || gemm1 -> (flags) -> gemm2 ----------------
// y in [0, CVT_ROWS):            W2 fp32->fp16 conversion (first-wave blocks)
// y in [G1_Y0, G2_Y0):           gemm1 tile ty = y - G1_Y0, col = blockIdx.x
// y in [G2_Y0, G2_Y0 + G2_ROWS): gemm2, lin = (y-G2_Y0)*16 + x -> (ty = lin/8, col = lin%8)
__global__ void __launch_bounds__(NTHREADS, 2) k_fused(
    const float* __restrict__ b1, const float* __restrict__ b2,
    float* __restrict__ out, const float* __restrict__ w2raw)
{
    extern __shared__ char smem[];
    int tid = threadIdx.x;
    int y   = blockIdx.y;

    if (y < CVT_ROWS) {
        size_t nb  = (size_t)CVT_ROWS * gridDim.x;
        size_t bid = (size_t)y * gridDim.x + blockIdx.x;
        for (size_t j = bid * NTHREADS + tid; j < N8_W2; j += nb * NTHREADS)
            cvt_chunk(w2raw, g_w2h, j);
        __threadfence();             // each thread's w2h stores visible
        __syncthreads();
        if (tid == 0) atomicAdd(&g_w2done, 1);
        return;
    }

    if (y < G2_Y0) {
        // ---- gemm1 ----
        int ty = y - G1_Y0;
        if (ty >= g_ntiles) return;
        int e    = g_tile_e[ty];
        int row0 = g_tile_r0[ty];
        int base = g_padoff[e];
        int n0   = blockIdx.x * BN;
        gemm_tile<true, false>(DDIM, HDIM, e, row0, base, n0,
                               g_xh, g_w1h, b1, nullptr, smem);
        __threadfence();             // each thread's h stores visible at L2
        __syncthreads();
        if (tid == 0) atomicAdd(&g_done1[ty], 1);
        return;
    }

    // ---- gemm2 ----
    int lin = (y - G2_Y0) * gridDim.x + blockIdx.x;
    int ty  = lin >> 3;
    int col = lin & 7;
    if (ty >= g_ntiles) return;

    if (tid == 0) {
        while (*(volatile int*)&g_w2done != CVT_BLOCKS) __nanosleep(128);
        while (*(volatile int*)&g_done1[ty] != HDIM / BN) __nanosleep(128);
    }
    __syncthreads();                 // all threads see the observation
    // h reads below use cp.async.cg (L2-coherent), so no stale-L1 hazard

    int e    = g_tile_e[ty];
    int row0 = g_tile_r0[ty];
    int base = g_padoff[e];
    int n0   = col * BN;
    gemm_tile<false, true>(HDIM, ODIM, e, row0, base, n0,
                           g_hh, g_w2h, b2, out, smem);
}

// ---------------- launch ----------------
extern "C" void kernel_launch(void* const* d_in, const int* in_sizes, int n_in,
                              void* d_out, int out_size) {
    const float* x    = (const float*)d_in[0];
    const float* W1   = (const float*)d_in[1];
    const float* b1   = (const float*)d_in[2];
    const float* W2   = (const float*)d_in[3];
    const float* b2   = (const float*)d_in[4];
    const int*   eidx = (const int*)  d_in[5];
    float* out = (float*)d_out;

    cudaFuncSetAttribute((const void*)k_fused,
                         cudaFuncAttributeMaxDynamicSharedMemorySize, SMEM_BYTES);

    // routing + tile table + flags + onehot (block 0) || cvt x,W1 (blocks 1..768)
    k_pre<<<1 + PRE_CVT_BLOCKS, 1024>>>(eidx, x, W1, out);

    // fused: W2-cvt (128 blocks) || gemm1 (72x16) -> flags -> gemm2 (36x16)
    dim3 gf(HDIM / BN, CVT_ROWS + MAXTILES + G2_ROWS, 1);   // (16, 116)
    k_fused<<<gf, NTHREADS, SMEM_BYTES>>>(b1, b2, out, W2);
}